// round 4
// baseline (speedup 1.0000x reference)
#include <cuda_runtime.h>
#include <math.h>
#include <stdint.h>

#define HSZ 1024
#define NHD 16
#define HDM 64
#define SEQ 2048
#define BSZ 2
#define NROWS (BSZ*SEQ)         /* 4096 */
#define NSTAT (BSZ*NHD*SEQ)     /* 65536 */

// -------- scratch (device globals; no allocations allowed) -----------------
__device__ float g_Q [NROWS*HSZ];
__device__ float g_K [NROWS*HSZ];
__device__ float g_V [NROWS*HSZ];
__device__ float g_GK[NROWS*HSZ];
__device__ float g_Xt[NROWS*HSZ];      // tf32-rounded X
__device__ float g_Wt[4*HSZ*HSZ];      // tf32-rounded Wq,Wk,Wv,Wgk
__device__ float g_GQ[BSZ*HSZ];
__device__ float g_gov[NSTAT];
__device__ float g_ent[NSTAT];
__device__ float g_mxp[NSTAT];

// -------- tf32 helpers ------------------------------------------------------
__device__ __forceinline__ float f2tf(float x){
    uint32_t u; asm("cvt.rna.tf32.f32 %0, %1;" : "=r"(u) : "f"(x));
    return __uint_as_float(u);
}
__device__ __forceinline__ void mma8(float c[4], const uint32_t a[4], const uint32_t b[2]){
    asm volatile("mma.sync.aligned.m16n8k8.row.col.f32.tf32.tf32.f32 "
        "{%0,%1,%2,%3}, {%4,%5,%6,%7}, {%8,%9}, {%0,%1,%2,%3};"
        : "+f"(c[0]), "+f"(c[1]), "+f"(c[2]), "+f"(c[3])
        : "r"(a[0]), "r"(a[1]), "r"(a[2]), "r"(a[3]), "r"(b[0]), "r"(b[1]));
}
// permute k within 8-groups so (k, k+4) are adjacent -> LDS.64 fragment loads
__device__ __forceinline__ int pe(int e){ return ((e&3)<<1) | ((e>>2)&1); }

// ===========================================================================
// Pre-round: RNA tf32-round X and the 4 weight matrices into scratch.
// ===========================================================================
__global__ void round_kernel(const float* __restrict__ X,
                             const float* __restrict__ Wq, const float* __restrict__ Wk,
                             const float* __restrict__ Wv, const float* __restrict__ Wg)
{
    const int n4x = NROWS*HSZ/4;
    const int n4w = HSZ*HSZ/4;
    const int tot = n4x + 4*n4w;
    for (int idx = blockIdx.x*blockDim.x + threadIdx.x; idx < tot;
         idx += gridDim.x*blockDim.x) {
        const float* s; float* d; int off;
        if (idx < n4x) { s = X; d = g_Xt; off = idx; }
        else {
            int w = (idx - n4x) / n4w;
            off = (idx - n4x) - w*n4w;
            s = (w==0) ? Wq : (w==1) ? Wk : (w==2) ? Wv : Wg;
            d = g_Wt + (size_t)w*HSZ*HSZ;
        }
        float4 v = ((const float4*)s)[off];
        float4 o = make_float4(f2tf(v.x), f2tf(v.y), f2tf(v.z), f2tf(v.w));
        ((float4*)d)[off] = o;
    }
}

// ===========================================================================
// Projection GEMM (tf32 tensor cores, double-buffered global loads):
// out = Xt[4096,1024] @ Wt[z] + b. z: 0=Q 1=K 2=V 3=GK.
// Q/K/V outputs are RNA-rounded to tf32 so attn can stage raw bits.
// ===========================================================================
#define PLA 40
#define PLB 136

__global__ __launch_bounds__(256,2) void proj_kernel(
    const float* __restrict__ bq, const float* __restrict__ bk,
    const float* __restrict__ bv, const float* __restrict__ bg)
{
    __shared__ float As[128*PLA];
    __shared__ float Bs[32*PLB];

    const float* bias; float* out;
    switch (blockIdx.z) {
        case 0:  bias = bq; out = g_Q;  break;
        case 1:  bias = bk; out = g_K;  break;
        case 2:  bias = bv; out = g_V;  break;
        default: bias = bg; out = g_GK; break;
    }
    const bool rnd = (blockIdx.z != 3);
    const float* Xp = g_Xt;
    const float* W  = g_Wt + (size_t)blockIdx.z*HSZ*HSZ;

    const int t = threadIdx.x;
    const int lane = t & 31, warp = t >> 5;
    const int qr = lane >> 2, qc = lane & 3;
    const int wm = warp >> 1, wn = warp & 1;
    const int r0 = blockIdx.y * 128, c0 = blockIdx.x * 128;

    const int ra_r = t >> 3,  ra_c = (t & 7) << 2;     // A: row, k-col
    const int rb_r = t >> 5,  rb_c = (t & 31) << 2;    // B: k-row, n-col

    float4 ra[4], rb[4];
#pragma unroll
    for (int i = 0; i < 4; i++) {
        ra[i] = *(const float4*)&Xp[(size_t)(r0 + ra_r + 32*i)*HSZ + ra_c];
        rb[i] = *(const float4*)&W [(size_t)(rb_r + 8*i)*HSZ + c0 + rb_c];
    }

    float acc[2][8][4];
#pragma unroll
    for (int mt = 0; mt < 2; mt++)
#pragma unroll
        for (int nt = 0; nt < 8; nt++)
#pragma unroll
            for (int k = 0; k < 4; k++) acc[mt][nt][k] = 0.f;

    for (int k0 = 0; k0 < HSZ; k0 += 32) {
        // store staged tile
#pragma unroll
        for (int i = 0; i < 4; i++) {
            float* p = &As[(ra_r + 32*i)*PLA + (ra_c & ~7)];
            int e = ra_c & 7;
            p[pe(e+0)] = ra[i].x; p[pe(e+1)] = ra[i].y;
            p[pe(e+2)] = ra[i].z; p[pe(e+3)] = ra[i].w;
            *(float4*)&Bs[(rb_r + 8*i)*PLB + rb_c] = rb[i];
        }
        __syncthreads();

        // prefetch next tile
        if (k0 + 32 < HSZ) {
#pragma unroll
            for (int i = 0; i < 4; i++) {
                ra[i] = *(const float4*)&Xp[(size_t)(r0 + ra_r + 32*i)*HSZ + k0+32 + ra_c];
                rb[i] = *(const float4*)&W [(size_t)(k0+32 + rb_r + 8*i)*HSZ + c0 + rb_c];
            }
        }

#pragma unroll
        for (int u = 0; u < 4; u++) {
            uint32_t af[2][4];
#pragma unroll
            for (int mt = 0; mt < 2; mt++) {
                int rm = wm*32 + mt*16;
                float2 lo = *(const float2*)&As[(rm+qr  )*PLA + u*8 + 2*qc];
                float2 hi = *(const float2*)&As[(rm+qr+8)*PLA + u*8 + 2*qc];
                af[mt][0] = __float_as_uint(lo.x); af[mt][1] = __float_as_uint(hi.x);
                af[mt][2] = __float_as_uint(lo.y); af[mt][3] = __float_as_uint(hi.y);
            }
#pragma unroll
            for (int nt = 0; nt < 8; nt++) {
                int col = wn*64 + nt*8 + qr;
                uint32_t bb[2];
                bb[0] = __float_as_uint(Bs[(u*8+qc  )*PLB + col]);
                bb[1] = __float_as_uint(Bs[(u*8+qc+4)*PLB + col]);
                mma8(acc[0][nt], af[0], bb);
                mma8(acc[1][nt], af[1], bb);
            }
        }
        __syncthreads();
    }

#pragma unroll
    for (int mt = 0; mt < 2; mt++) {
        int rm = r0 + wm*32 + mt*16;
#pragma unroll
        for (int nt = 0; nt < 8; nt++) {
            int col = c0 + wn*64 + nt*8 + 2*qc;
            float b0 = bias[col], b1 = bias[col+1];
            float2 o;
            o.x = acc[mt][nt][0] + b0; o.y = acc[mt][nt][1] + b1;
            if (rnd) { o.x = f2tf(o.x); o.y = f2tf(o.y); }
            *(float2*)&out[(size_t)(rm+qr)*HSZ + col] = o;
            o.x = acc[mt][nt][2] + b0; o.y = acc[mt][nt][3] + b1;
            if (rnd) { o.x = f2tf(o.x); o.y = f2tf(o.y); }
            *(float2*)&out[(size_t)(rm+qr+8)*HSZ + col] = o;
        }
    }
}

// ===========================================================================
// gq = governance_embeddings[2,1024] @ Wgq + bgq   (tiny, SIMT, fp32)
// ===========================================================================
__global__ void gq_kernel(const float* __restrict__ ge,
                          const float* __restrict__ W,
                          const float* __restrict__ bias)
{
    int c = blockIdx.x * blockDim.x + threadIdx.x;
    int r = blockIdx.y;
    const float* g = ge + (size_t)r * HSZ;
    float a0 = 0.f, a1 = 0.f, a2 = 0.f, a3 = 0.f;
    for (int k = 0; k < HSZ; k += 4) {
        a0 += g[k+0] * W[(size_t)(k+0)*HSZ + c];
        a1 += g[k+1] * W[(size_t)(k+1)*HSZ + c];
        a2 += g[k+2] * W[(size_t)(k+2)*HSZ + c];
        a3 += g[k+3] * W[(size_t)(k+3)*HSZ + c];
    }
    g_GQ[(size_t)r*HSZ + c] = (a0+a1) + (a2+a3) + bias[c];
}

// ===========================================================================
// gov_scores[b,h,s] = sum_d gq[b,h,d]*gk[b,s,h,d]. One warp per output.
// ===========================================================================
__global__ void gov_kernel()
{
    int gw   = (blockIdx.x * blockDim.x + threadIdx.x) >> 5;
    int lane = threadIdx.x & 31;
    if (gw >= NSTAT) return;
    int s  = gw & (SEQ-1);
    int bh = gw >> 11;
    int b = bh >> 4, h = bh & 15;
    const float* gq = g_GQ + (size_t)b*HSZ + h*HDM;
    const float* gk = g_GK + ((size_t)(b*SEQ + s))*HSZ + h*HDM;
    float acc = gq[lane]*gk[lane] + gq[lane+32]*gk[lane+32];
#pragma unroll
    for (int o = 16; o; o >>= 1)
        acc += __shfl_xor_sync(0xffffffffu, acc, o);
    if (lane == 0) g_gov[gw] = acc;
}

// ===========================================================================
// Flash attention, tf32 tensor cores, no P bridge:
// S-accumulator C-fragment is reused directly as the PV A-fragment
// (reorder {c0,c2,c1,c3}; V k-rows fetched as (2qc, 2qc+1)).
// ===========================================================================
#define ALD 72   /* qs/ks stride: 72 mod 32 == 8 */
#define VLD 68   /* vs stride: 68 mod 32 == 4 -> conflict-free PV B loads */
#define QS_OFF 0
#define KS_OFF (128*ALD)
#define VS_OFF (KS_OFF + 64*ALD)
#define ATT_SMEM ((VS_OFF + 64*VLD)*4)   /* 72704 bytes -> 3 CTAs/SM */

__global__ __launch_bounds__(128,3) void attn_kernel(float* __restrict__ ctx)
{
    extern __shared__ float sm[];
    float* qs = sm + QS_OFF;   // 128 x 64, k-permuted (already tf32)
    float* ks = sm + KS_OFF;   // 64 x 64, k-permuted
    float* vs = sm + VS_OFF;   // 64 x 64, natural [j][d]

    const int t = threadIdx.x;
    const int lane = t & 31, warp = t >> 5;
    const int qr = lane >> 2, qc = lane & 3;
    const int bh = blockIdx.y, b = bh >> 4, h = bh & 15;
    const int q0 = blockIdx.x * 128;
    const int wr = warp * 32;

    const float* Qg = g_Q + ((size_t)(b*SEQ + q0))*HSZ + h*HDM;
    const float* Kg = g_K + ((size_t)(b*SEQ))*HSZ + h*HDM;
    const float* Vg = g_V + ((size_t)(b*SEQ))*HSZ + h*HDM;

    // stage Q (coalesced, permuted; values pre-rounded by proj epilogue)
    for (int idx = t; idx < 2048; idx += 128) {
        int r = idx >> 4, c = (idx & 15) << 2;
        float4 v = *(const float4*)&Qg[(size_t)r*HSZ + c];
        float* p = &qs[r*ALD + (c & ~7)];
        int e = c & 7;
        p[pe(e+0)] = v.x; p[pe(e+1)] = v.y; p[pe(e+2)] = v.z; p[pe(e+3)] = v.w;
    }

    float O[2][8][4];
    float m[2][2], Z[2][2], T[2][2], E[2][2];
#pragma unroll
    for (int mt = 0; mt < 2; mt++) {
#pragma unroll
        for (int hi = 0; hi < 2; hi++) {
            m[mt][hi] = -1e30f; Z[mt][hi] = 0.f; T[mt][hi] = 0.f; E[mt][hi] = 0.f;
        }
#pragma unroll
        for (int nt = 0; nt < 8; nt++)
#pragma unroll
            for (int k = 0; k < 4; k++) O[mt][nt][k] = 0.f;
    }

    for (int j0 = 0; j0 < SEQ; j0 += 64) {
        __syncthreads();   // prior tile's reads of ks/vs done (also covers Q stage)
        for (int idx = t; idx < 1024; idx += 128) {
            int r = idx >> 4, c = (idx & 15) << 2;
            float4 kv = *(const float4*)&Kg[(size_t)(j0+r)*HSZ + c];
            float* p = &ks[r*ALD + (c & ~7)];
            int e = c & 7;
            p[pe(e+0)] = kv.x; p[pe(e+1)] = kv.y; p[pe(e+2)] = kv.z; p[pe(e+3)] = kv.w;
            *(float4*)&vs[r*VLD + c] = *(const float4*)&Vg[(size_t)(j0+r)*HSZ + c];
        }
        __syncthreads();

        // ---- S = Q @ K^T ----
        float sc[2][8][4];
#pragma unroll
        for (int mt = 0; mt < 2; mt++)
#pragma unroll
            for (int nt = 0; nt < 8; nt++)
#pragma unroll
                for (int k = 0; k < 4; k++) sc[mt][nt][k] = 0.f;

#pragma unroll
        for (int u = 0; u < 8; u++) {
            uint32_t qa[2][4];
#pragma unroll
            for (int mt = 0; mt < 2; mt++) {
                int rm = wr + mt*16;
                float2 lo = *(const float2*)&qs[(rm+qr  )*ALD + u*8 + 2*qc];
                float2 hi = *(const float2*)&qs[(rm+qr+8)*ALD + u*8 + 2*qc];
                qa[mt][0] = __float_as_uint(lo.x); qa[mt][1] = __float_as_uint(hi.x);
                qa[mt][2] = __float_as_uint(lo.y); qa[mt][3] = __float_as_uint(hi.y);
            }
#pragma unroll
            for (int nt = 0; nt < 8; nt++) {
                float2 kb = *(const float2*)&ks[(nt*8+qr)*ALD + u*8 + 2*qc];
                uint32_t bb[2] = { __float_as_uint(kb.x), __float_as_uint(kb.y) };
                mma8(sc[0][nt], qa[0], bb);
                mma8(sc[1][nt], qa[1], bb);
            }
        }

        // ---- online softmax + stats ----
#pragma unroll
        for (int mt = 0; mt < 2; mt++) {
#pragma unroll
            for (int hi = 0; hi < 2; hi++) {
                float lm = -1e30f;
#pragma unroll
                for (int nt = 0; nt < 8; nt++) {
                    sc[mt][nt][2*hi  ] *= 0.125f;
                    sc[mt][nt][2*hi+1] *= 0.125f;
                    lm = fmaxf(lm, fmaxf(sc[mt][nt][2*hi], sc[mt][nt][2*hi+1]));
                }
                lm = fmaxf(lm, __shfl_xor_sync(0xffffffffu, lm, 1));
                lm = fmaxf(lm, __shfl_xor_sync(0xffffffffu, lm, 2));
                float mo = m[mt][hi];
                float mn = fmaxf(mo, lm);
                float al = __expf(mo - mn);
                T[mt][hi] = al * (T[mt][hi] + (mo - mn) * Z[mt][hi]);
                Z[mt][hi] *= al;
                E[mt][hi] *= al;
#pragma unroll
                for (int nt = 0; nt < 8; nt++) {
                    O[mt][nt][2*hi  ] *= al;
                    O[mt][nt][2*hi+1] *= al;
                }
                m[mt][hi] = mn;
                float sp = 0.f, st = 0.f, pm = 0.f;
#pragma unroll
                for (int nt = 0; nt < 8; nt++) {
#pragma unroll
                    for (int k = 0; k < 2; k++) {
                        float d = sc[mt][nt][2*hi+k] - mn;
                        float p = __expf(d);
                        sp += p; st += p*d; pm = fmaxf(pm, p);
                        sc[mt][nt][2*hi+k] = f2tf(p);   // rounded for the PV mma
                    }
                }
                sp += __shfl_xor_sync(0xffffffffu, sp, 1);
                sp += __shfl_xor_sync(0xffffffffu, sp, 2);
                st += __shfl_xor_sync(0xffffffffu, st, 1);
                st += __shfl_xor_sync(0xffffffffu, st, 2);
                pm  = fmaxf(pm, __shfl_xor_sync(0xffffffffu, pm, 1));
                pm  = fmaxf(pm, __shfl_xor_sync(0xffffffffu, pm, 2));
                Z[mt][hi] += sp; T[mt][hi] += st; E[mt][hi] = fmaxf(E[mt][hi], pm);
            }
        }

        // ---- O += P @ V : sc fragment reused directly as A-fragment ----
#pragma unroll
        for (int u = 0; u < 8; u++) {
            uint32_t pa[2][4];
#pragma unroll
            for (int mt = 0; mt < 2; mt++) {
                pa[mt][0] = __float_as_uint(sc[mt][u][0]);
                pa[mt][1] = __float_as_uint(sc[mt][u][2]);
                pa[mt][2] = __float_as_uint(sc[mt][u][1]);
                pa[mt][3] = __float_as_uint(sc[mt][u][3]);
            }
#pragma unroll
            for (int nt = 0; nt < 8; nt++) {
                uint32_t bb[2];
                bb[0] = __float_as_uint(vs[(u*8 + 2*qc    )*VLD + nt*8 + qr]);
                bb[1] = __float_as_uint(vs[(u*8 + 2*qc + 1)*VLD + nt*8 + qr]);
                mma8(O[0][nt], pa[0], bb);
                mma8(O[1][nt], pa[1], bb);
            }
        }
    }

    // ---- epilogue: normalize, write context + per-row stats ----
#pragma unroll
    for (int mt = 0; mt < 2; mt++) {
        int rml = wr + mt*16;
#pragma unroll
        for (int hi = 0; hi < 2; hi++) {
            int row = rml + qr + 8*hi;
            float iz = 1.0f / Z[mt][hi];
#pragma unroll
            for (int nt = 0; nt < 8; nt++) {
                float2 o;
                o.x = O[mt][nt][2*hi  ] * iz;
                o.y = O[mt][nt][2*hi+1] * iz;
                *(float2*)&ctx[((size_t)(b*SEQ + q0 + row))*HSZ + h*HDM + nt*8 + 2*qc] = o;
            }
            if (qc == 0) {
                int idx = bh*SEQ + q0 + row;
                g_ent[idx] = logf(Z[mt][hi]) - T[mt][hi]*iz;
                g_mxp[idx] = E[mt][hi]*iz;
            }
        }
    }
}

// ===========================================================================
// Deterministic final reduction: 3 scalar means (no atomics).
// ===========================================================================
__global__ void reduce_kernel(float* __restrict__ out, int n_ctx)
{
    __shared__ float se[512], si[512], sc[512];
    int t = threadIdx.x;
    float e = 0.f, i = 0.f, c = 0.f;
    for (int l = t; l < NSTAT; l += 512) {
        e += g_ent[l];
        i += fabsf(g_gov[l]);
        c += g_mxp[l];
    }
    se[t] = e; si[t] = i; sc[t] = c;
    __syncthreads();
    for (int s2 = 256; s2 > 0; s2 >>= 1) {
        if (t < s2) { se[t] += se[t+s2]; si[t] += si[t+s2]; sc[t] += sc[t+s2]; }
        __syncthreads();
    }
    if (t == 0) {
        const float inv = 1.0f / (float)NSTAT;
        out[n_ctx + 0] = se[0] * inv;
        out[n_ctx + 1] = si[0] * inv;
        out[n_ctx + 2] = sc[0] * inv;
    }
}

// ===========================================================================
extern "C" void kernel_launch(void* const* d_in, const int* in_sizes, int n_in,
                              void* d_out, int out_size)
{
    const float* X   = (const float*)d_in[0];
    const float* GE  = (const float*)d_in[1];
    const float* Wq  = (const float*)d_in[2];  const float* bq  = (const float*)d_in[3];
    const float* Wk  = (const float*)d_in[4];  const float* bk  = (const float*)d_in[5];
    const float* Wv  = (const float*)d_in[6];  const float* bv  = (const float*)d_in[7];
    const float* Wgq = (const float*)d_in[8];  const float* bgq = (const float*)d_in[9];
    const float* Wgk = (const float*)d_in[10]; const float* bgk = (const float*)d_in[11];
    float* out = (float*)d_out;

    cudaFuncSetAttribute(attn_kernel, cudaFuncAttributeMaxDynamicSharedMemorySize, ATT_SMEM);

    round_kernel<<<1024, 256>>>(X, Wq, Wk, Wv, Wgk);
    proj_kernel<<<dim3(8, 32, 4), 256>>>(bq, bk, bv, bgk);
    gq_kernel<<<dim3(4, 2), 256>>>(GE, Wgq, bgq);
    gov_kernel<<<NSTAT*32/256, 256>>>();
    attn_kernel<<<dim3(SEQ/128, BSZ*NHD), 128, ATT_SMEM>>>(out);
    reduce_kernel<<<1, 512>>>(out, out_size - 3);
}

// round 5
// speedup vs baseline: 1.1163x; 1.1163x over previous
#include <cuda_runtime.h>
#include <math.h>
#include <stdint.h>

#define HSZ 1024
#define NHD 16
#define HDM 64
#define SEQ 2048
#define BSZ 2
#define NROWS (BSZ*SEQ)         /* 4096 */
#define NSTAT (BSZ*NHD*SEQ)     /* 65536 */

// -------- scratch (device globals; no allocations allowed) -----------------
__device__ float g_Q [NROWS*HSZ];
__device__ float g_K [NROWS*HSZ];
__device__ float g_V [NROWS*HSZ];
__device__ float g_GK[NROWS*HSZ];
__device__ float g_GQ[BSZ*HSZ];
__device__ float g_gov[NSTAT];
__device__ float g_ent[NSTAT];
__device__ float g_mxp[NSTAT];

// -------- tf32 helpers ------------------------------------------------------
__device__ __forceinline__ float f2tf(float x){
    uint32_t u; asm("cvt.rna.tf32.f32 %0, %1;" : "=r"(u) : "f"(x));
    return __uint_as_float(u);
}
__device__ __forceinline__ void mma8(float c[4], const uint32_t a[4], const uint32_t b[2]){
    asm volatile("mma.sync.aligned.m16n8k8.row.col.f32.tf32.tf32.f32 "
        "{%0,%1,%2,%3}, {%4,%5,%6,%7}, {%8,%9}, {%0,%1,%2,%3};"
        : "+f"(c[0]), "+f"(c[1]), "+f"(c[2]), "+f"(c[3])
        : "r"(a[0]), "r"(a[1]), "r"(a[2]), "r"(a[3]), "r"(b[0]), "r"(b[1]));
}
// permute k within 8-groups so (k, k+4) are adjacent -> LDS.64 fragment loads
__device__ __forceinline__ int pe(int e){ return ((e&3)<<1) | ((e>>2)&1); }

// ===========================================================================
// Projection GEMM (tf32 tensor cores) — round-2 proven version.
// out = X[4096,1024] @ W[1024,1024] + b for Q/K/V/GK (z selects matrix).
// CTA tile 128x128, BK=32, 8 warps each 32x64.
// ===========================================================================
#define PLA 40    /* As row stride; 40 mod 32 == 8 -> conflict-free */
#define PLB 136   /* Bs row stride; 136 mod 32 == 8 -> conflict-free */

__global__ __launch_bounds__(256) void proj_kernel(
    const float* __restrict__ X,
    const float* __restrict__ Wq, const float* __restrict__ bq,
    const float* __restrict__ Wk, const float* __restrict__ bk,
    const float* __restrict__ Wv, const float* __restrict__ bv,
    const float* __restrict__ Wg, const float* __restrict__ bg)
{
    __shared__ float As[128*PLA];
    __shared__ float Bs[32*PLB];

    const float* W; const float* bias; float* out;
    switch (blockIdx.z) {
        case 0:  W = Wq; bias = bq; out = g_Q;  break;
        case 1:  W = Wk; bias = bk; out = g_K;  break;
        case 2:  W = Wv; bias = bv; out = g_V;  break;
        default: W = Wg; bias = bg; out = g_GK; break;
    }

    const int t = threadIdx.x;
    const int lane = t & 31, warp = t >> 5;
    const int qr = lane >> 2, qc = lane & 3;
    const int wm = warp >> 1, wn = warp & 1;
    const int r0 = blockIdx.y * 128, c0 = blockIdx.x * 128;

    float acc[2][8][4];
#pragma unroll
    for (int mt = 0; mt < 2; mt++)
#pragma unroll
        for (int nt = 0; nt < 8; nt++)
#pragma unroll
            for (int k = 0; k < 4; k++) acc[mt][nt][k] = 0.f;

    for (int k0 = 0; k0 < HSZ; k0 += 32) {
#pragma unroll
        for (int i = 0; i < 4; i++) {
            int idx = t + i*256;
            int r = idx >> 3, c = (idx & 7) << 2;
            float4 v = *(const float4*)&X[(size_t)(r0+r)*HSZ + k0 + c];
            float* p = &As[r*PLA + (c & ~7)];
            int e = c & 7;
            p[pe(e+0)] = f2tf(v.x); p[pe(e+1)] = f2tf(v.y);
            p[pe(e+2)] = f2tf(v.z); p[pe(e+3)] = f2tf(v.w);
        }
#pragma unroll
        for (int i = 0; i < 4; i++) {
            int idx = t + i*256;
            int r = idx >> 5, c = (idx & 31) << 2;
            float4 v = *(const float4*)&W[(size_t)(k0+r)*HSZ + c0 + c];
            float4 o = make_float4(f2tf(v.x), f2tf(v.y), f2tf(v.z), f2tf(v.w));
            *(float4*)&Bs[r*PLB + c] = o;
        }
        __syncthreads();

#pragma unroll
        for (int u = 0; u < 4; u++) {
            uint32_t af[2][4];
#pragma unroll
            for (int mt = 0; mt < 2; mt++) {
                int rm = wm*32 + mt*16;
                float2 lo = *(const float2*)&As[(rm+qr  )*PLA + u*8 + 2*qc];
                float2 hi = *(const float2*)&As[(rm+qr+8)*PLA + u*8 + 2*qc];
                af[mt][0] = __float_as_uint(lo.x); af[mt][1] = __float_as_uint(hi.x);
                af[mt][2] = __float_as_uint(lo.y); af[mt][3] = __float_as_uint(hi.y);
            }
#pragma unroll
            for (int nt = 0; nt < 8; nt++) {
                int col = wn*64 + nt*8 + qr;
                uint32_t bb[2];
                bb[0] = __float_as_uint(Bs[(u*8+qc  )*PLB + col]);
                bb[1] = __float_as_uint(Bs[(u*8+qc+4)*PLB + col]);
                mma8(acc[0][nt], af[0], bb);
                mma8(acc[1][nt], af[1], bb);
            }
        }
        __syncthreads();
    }

#pragma unroll
    for (int mt = 0; mt < 2; mt++) {
        int rm = r0 + wm*32 + mt*16;
#pragma unroll
        for (int nt = 0; nt < 8; nt++) {
            int col = c0 + wn*64 + nt*8 + 2*qc;
            float b0 = bias[col], b1 = bias[col+1];
            float2 o;
            o.x = acc[mt][nt][0] + b0; o.y = acc[mt][nt][1] + b1;
            *(float2*)&out[(size_t)(rm+qr)*HSZ + col] = o;
            o.x = acc[mt][nt][2] + b0; o.y = acc[mt][nt][3] + b1;
            *(float2*)&out[(size_t)(rm+qr+8)*HSZ + col] = o;
        }
    }
}

// ===========================================================================
// gq = governance_embeddings[2,1024] @ Wgq + bgq   (tiny, SIMT, fp32)
// ===========================================================================
__global__ void gq_kernel(const float* __restrict__ ge,
                          const float* __restrict__ W,
                          const float* __restrict__ bias)
{
    int c = blockIdx.x * blockDim.x + threadIdx.x;
    int r = blockIdx.y;
    const float* g = ge + (size_t)r * HSZ;
    float a0 = 0.f, a1 = 0.f, a2 = 0.f, a3 = 0.f;
    for (int k = 0; k < HSZ; k += 4) {
        a0 += g[k+0] * W[(size_t)(k+0)*HSZ + c];
        a1 += g[k+1] * W[(size_t)(k+1)*HSZ + c];
        a2 += g[k+2] * W[(size_t)(k+2)*HSZ + c];
        a3 += g[k+3] * W[(size_t)(k+3)*HSZ + c];
    }
    g_GQ[(size_t)r*HSZ + c] = (a0+a1) + (a2+a3) + bias[c];
}

// ===========================================================================
// gov_scores[b,h,s] = sum_d gq[b,h,d]*gk[b,s,h,d]. One warp per output.
// ===========================================================================
__global__ void gov_kernel()
{
    int gw   = (blockIdx.x * blockDim.x + threadIdx.x) >> 5;
    int lane = threadIdx.x & 31;
    if (gw >= NSTAT) return;
    int s  = gw & (SEQ-1);
    int bh = gw >> 11;
    int b = bh >> 4, h = bh & 15;
    const float* gq = g_GQ + (size_t)b*HSZ + h*HDM;
    const float* gk = g_GK + ((size_t)(b*SEQ + s))*HSZ + h*HDM;
    float acc = gq[lane]*gk[lane] + gq[lane+32]*gk[lane+32];
#pragma unroll
    for (int o = 16; o; o >>= 1)
        acc += __shfl_xor_sync(0xffffffffu, acc, o);
    if (lane == 0) g_gov[gw] = acc;
}

// ===========================================================================
// Flash attention, tf32 tensor cores, 256 threads / 8 warps x 16 rows.
// No P smem bridge: S C-fragment reused directly as the PV A-fragment
// (reorder {c0,c2,c1,c3}; V k-rows fetched as (2qc, 2qc+1)).
// ===========================================================================
#define ALD 72   /* qs/ks stride: 72 mod 32 == 8 */
#define VLD 68   /* vs stride: 68 mod 32 == 4 -> conflict-free PV B loads */
#define QS_OFF 0
#define KS_OFF (128*ALD)
#define VS_OFF (KS_OFF + 64*ALD)
#define ATT_SMEM ((VS_OFF + 64*VLD)*4)   /* 72704 bytes */

__global__ __launch_bounds__(256) void attn_kernel(float* __restrict__ ctx)
{
    extern __shared__ float sm[];
    float* qs = sm + QS_OFF;   // 128 x 64, k-permuted
    float* ks = sm + KS_OFF;   // 64 x 64, k-permuted
    float* vs = sm + VS_OFF;   // 64 x 64, natural [j][d]

    const int t = threadIdx.x;
    const int lane = t & 31, warp = t >> 5;
    const int qr = lane >> 2, qc = lane & 3;
    const int bh = blockIdx.y, b = bh >> 4, h = bh & 15;
    const int q0 = blockIdx.x * 128;
    const int wr = warp * 16;          // each warp owns 16 rows

    const float* Qg = g_Q + ((size_t)(b*SEQ + q0))*HSZ + h*HDM;
    const float* Kg = g_K + ((size_t)(b*SEQ))*HSZ + h*HDM;
    const float* Vg = g_V + ((size_t)(b*SEQ))*HSZ + h*HDM;

    // stage Q (coalesced, tf32, permuted)
    for (int idx = t; idx < 2048; idx += 256) {
        int r = idx >> 4, c = (idx & 15) << 2;
        float4 v = *(const float4*)&Qg[(size_t)r*HSZ + c];
        float* p = &qs[r*ALD + (c & ~7)];
        int e = c & 7;
        p[pe(e+0)] = f2tf(v.x); p[pe(e+1)] = f2tf(v.y);
        p[pe(e+2)] = f2tf(v.z); p[pe(e+3)] = f2tf(v.w);
    }

    float O[8][4];
    float m[2], Z[2], T[2], E[2];
#pragma unroll
    for (int hi = 0; hi < 2; hi++) { m[hi] = -1e30f; Z[hi] = 0.f; T[hi] = 0.f; E[hi] = 0.f; }
#pragma unroll
    for (int nt = 0; nt < 8; nt++)
#pragma unroll
        for (int k = 0; k < 4; k++) O[nt][k] = 0.f;

    for (int j0 = 0; j0 < SEQ; j0 += 64) {
        __syncthreads();   // prior tile's reads of ks/vs done (also covers Q stage)
        for (int idx = t; idx < 1024; idx += 256) {
            int r = idx >> 4, c = (idx & 15) << 2;
            float4 kv = *(const float4*)&Kg[(size_t)(j0+r)*HSZ + c];
            float* p = &ks[r*ALD + (c & ~7)];
            int e = c & 7;
            p[pe(e+0)] = f2tf(kv.x); p[pe(e+1)] = f2tf(kv.y);
            p[pe(e+2)] = f2tf(kv.z); p[pe(e+3)] = f2tf(kv.w);
            float4 vv = *(const float4*)&Vg[(size_t)(j0+r)*HSZ + c];
            float4 vo = make_float4(f2tf(vv.x), f2tf(vv.y), f2tf(vv.z), f2tf(vv.w));
            *(float4*)&vs[r*VLD + c] = vo;
        }
        __syncthreads();

        // ---- S = Q @ K^T  (one 16-row m-tile per warp) ----
        float sc[8][4];
#pragma unroll
        for (int nt = 0; nt < 8; nt++)
#pragma unroll
            for (int k = 0; k < 4; k++) sc[nt][k] = 0.f;

#pragma unroll
        for (int u = 0; u < 8; u++) {
            uint32_t qa[4];
            {
                float2 lo = *(const float2*)&qs[(wr+qr  )*ALD + u*8 + 2*qc];
                float2 hi = *(const float2*)&qs[(wr+qr+8)*ALD + u*8 + 2*qc];
                qa[0] = __float_as_uint(lo.x); qa[1] = __float_as_uint(hi.x);
                qa[2] = __float_as_uint(lo.y); qa[3] = __float_as_uint(hi.y);
            }
#pragma unroll
            for (int nt = 0; nt < 8; nt++) {
                float2 kb = *(const float2*)&ks[(nt*8+qr)*ALD + u*8 + 2*qc];
                uint32_t bb[2] = { __float_as_uint(kb.x), __float_as_uint(kb.y) };
                mma8(sc[nt], qa, bb);
            }
        }

        // ---- online softmax + stats (rows wr+qr, wr+qr+8) ----
#pragma unroll
        for (int hi = 0; hi < 2; hi++) {
            float lm = -1e30f;
#pragma unroll
            for (int nt = 0; nt < 8; nt++) {
                sc[nt][2*hi  ] *= 0.125f;
                sc[nt][2*hi+1] *= 0.125f;
                lm = fmaxf(lm, fmaxf(sc[nt][2*hi], sc[nt][2*hi+1]));
            }
            lm = fmaxf(lm, __shfl_xor_sync(0xffffffffu, lm, 1));
            lm = fmaxf(lm, __shfl_xor_sync(0xffffffffu, lm, 2));
            float mo = m[hi];
            float mn = fmaxf(mo, lm);
            float al = __expf(mo - mn);
            T[hi] = al * (T[hi] + (mo - mn) * Z[hi]);
            Z[hi] *= al;
            E[hi] *= al;
#pragma unroll
            for (int nt = 0; nt < 8; nt++) {
                O[nt][2*hi  ] *= al;
                O[nt][2*hi+1] *= al;
            }
            m[hi] = mn;
            float sp = 0.f, st = 0.f, pm = 0.f;
#pragma unroll
            for (int nt = 0; nt < 8; nt++) {
#pragma unroll
                for (int k = 0; k < 2; k++) {
                    float d = sc[nt][2*hi+k] - mn;
                    float p = __expf(d);
                    sp += p; st += p*d; pm = fmaxf(pm, p);
                    sc[nt][2*hi+k] = f2tf(p);   // rounded for the PV mma
                }
            }
            sp += __shfl_xor_sync(0xffffffffu, sp, 1);
            sp += __shfl_xor_sync(0xffffffffu, sp, 2);
            st += __shfl_xor_sync(0xffffffffu, st, 1);
            st += __shfl_xor_sync(0xffffffffu, st, 2);
            pm  = fmaxf(pm, __shfl_xor_sync(0xffffffffu, pm, 1));
            pm  = fmaxf(pm, __shfl_xor_sync(0xffffffffu, pm, 2));
            Z[hi] += sp; T[hi] += st; E[hi] = fmaxf(E[hi], pm);
        }

        // ---- O += P @ V : sc fragment reused directly as A-fragment ----
#pragma unroll
        for (int u = 0; u < 8; u++) {
            uint32_t pa[4];
            pa[0] = __float_as_uint(sc[u][0]);
            pa[1] = __float_as_uint(sc[u][2]);
            pa[2] = __float_as_uint(sc[u][1]);
            pa[3] = __float_as_uint(sc[u][3]);
#pragma unroll
            for (int nt = 0; nt < 8; nt++) {
                uint32_t bb[2];
                bb[0] = __float_as_uint(vs[(u*8 + 2*qc    )*VLD + nt*8 + qr]);
                bb[1] = __float_as_uint(vs[(u*8 + 2*qc + 1)*VLD + nt*8 + qr]);
                mma8(O[nt], pa, bb);
            }
        }
    }

    // ---- epilogue: normalize, write context + per-row stats ----
#pragma unroll
    for (int hi = 0; hi < 2; hi++) {
        int row = wr + qr + 8*hi;
        float iz = 1.0f / Z[hi];
#pragma unroll
        for (int nt = 0; nt < 8; nt++) {
            float2 o;
            o.x = O[nt][2*hi  ] * iz;
            o.y = O[nt][2*hi+1] * iz;
            *(float2*)&ctx[((size_t)(b*SEQ + q0 + row))*HSZ + h*HDM + nt*8 + 2*qc] = o;
        }
        if (qc == 0) {
            int idx = bh*SEQ + q0 + row;
            g_ent[idx] = logf(Z[hi]) - T[hi]*iz;
            g_mxp[idx] = E[hi]*iz;
        }
    }
}

// ===========================================================================
// Deterministic final reduction: 3 scalar means (no atomics).
// ===========================================================================
__global__ void reduce_kernel(float* __restrict__ out, int n_ctx)
{
    __shared__ float se[512], si[512], sc[512];
    int t = threadIdx.x;
    float e = 0.f, i = 0.f, c = 0.f;
    for (int l = t; l < NSTAT; l += 512) {
        e += g_ent[l];
        i += fabsf(g_gov[l]);
        c += g_mxp[l];
    }
    se[t] = e; si[t] = i; sc[t] = c;
    __syncthreads();
    for (int s2 = 256; s2 > 0; s2 >>= 1) {
        if (t < s2) { se[t] += se[t+s2]; si[t] += si[t+s2]; sc[t] += sc[t+s2]; }
        __syncthreads();
    }
    if (t == 0) {
        const float inv = 1.0f / (float)NSTAT;
        out[n_ctx + 0] = se[0] * inv;
        out[n_ctx + 1] = si[0] * inv;
        out[n_ctx + 2] = sc[0] * inv;
    }
}

// ===========================================================================
extern "C" void kernel_launch(void* const* d_in, const int* in_sizes, int n_in,
                              void* d_out, int out_size)
{
    const float* X   = (const float*)d_in[0];
    const float* GE  = (const float*)d_in[1];
    const float* Wq  = (const float*)d_in[2];  const float* bq  = (const float*)d_in[3];
    const float* Wk  = (const float*)d_in[4];  const float* bk  = (const float*)d_in[5];
    const float* Wv  = (const float*)d_in[6];  const float* bv  = (const float*)d_in[7];
    const float* Wgq = (const float*)d_in[8];  const float* bgq = (const float*)d_in[9];
    const float* Wgk = (const float*)d_in[10]; const float* bgk = (const float*)d_in[11];
    float* out = (float*)d_out;

    cudaFuncSetAttribute(attn_kernel, cudaFuncAttributeMaxDynamicSharedMemorySize, ATT_SMEM);

    proj_kernel<<<dim3(8, 32, 4), 256>>>(X, Wq, bq, Wk, bk, Wv, bv, Wgk, bgk);
    gq_kernel<<<dim3(4, 2), 256>>>(GE, Wgq, bgq);
    gov_kernel<<<NSTAT*32/256, 256>>>();
    attn_kernel<<<dim3(SEQ/128, BSZ*NHD), 256, ATT_SMEM>>>(out);
    reduce_kernel<<<1, 512>>>(out, out_size - 3);
}

// round 7
// speedup vs baseline: 1.2050x; 1.0794x over previous
#include <cuda_runtime.h>
#include <math.h>
#include <stdint.h>

#define HSZ 1024
#define NHD 16
#define HDM 64
#define SEQ 2048
#define BSZ 2
#define NROWS (BSZ*SEQ)         /* 4096 */
#define NSTAT (BSZ*NHD*SEQ)     /* 65536 */

// -------- scratch (device globals; no allocations allowed) -----------------
__device__ float g_Q [NROWS*HSZ];
__device__ float g_K [NROWS*HSZ];
__device__ float g_V [NROWS*HSZ];
__device__ float g_GK[NROWS*HSZ];
__device__ float g_GQ[BSZ*HSZ];
__device__ float g_gov[NSTAT];
__device__ float g_ent[NSTAT];
__device__ float g_mxp[NSTAT];

// -------- tf32 helpers ------------------------------------------------------
__device__ __forceinline__ float f2tf(float x){
    uint32_t u; asm("cvt.rna.tf32.f32 %0, %1;" : "=r"(u) : "f"(x));
    return __uint_as_float(u);
}
__device__ __forceinline__ void mma8(float c[4], const uint32_t a[4], const uint32_t b[2]){
    asm volatile("mma.sync.aligned.m16n8k8.row.col.f32.tf32.tf32.f32 "
        "{%0,%1,%2,%3}, {%4,%5,%6,%7}, {%8,%9}, {%0,%1,%2,%3};"
        : "+f"(c[0]), "+f"(c[1]), "+f"(c[2]), "+f"(c[3])
        : "r"(a[0]), "r"(a[1]), "r"(a[2]), "r"(a[3]), "r"(b[0]), "r"(b[1]));
}
// permute k within 8-groups so (k, k+4) are adjacent -> LDS.64 fragment loads
__device__ __forceinline__ int pe(int e){ return ((e&3)<<1) | ((e>>2)&1); }

// ===========================================================================
// Projection GEMM (tf32 tensor cores) — proven version, unchanged.
// out = X[4096,1024] @ W[1024,1024] + b for Q/K/V/GK (z selects matrix).
// CTA tile 128x128, BK=32, 8 warps each 32x64.
// ===========================================================================
#define PLA 40    /* As row stride; 40 mod 32 == 8 -> conflict-free */
#define PLB 136   /* Bs row stride; 136 mod 32 == 8 -> conflict-free */

__global__ __launch_bounds__(256) void proj_kernel(
    const float* __restrict__ X,
    const float* __restrict__ Wq, const float* __restrict__ bq,
    const float* __restrict__ Wk, const float* __restrict__ bk,
    const float* __restrict__ Wv, const float* __restrict__ bv,
    const float* __restrict__ Wg, const float* __restrict__ bg)
{
    __shared__ float As[128*PLA];
    __shared__ float Bs[32*PLB];

    const float* W; const float* bias; float* out;
    switch (blockIdx.z) {
        case 0:  W = Wq; bias = bq; out = g_Q;  break;
        case 1:  W = Wk; bias = bk; out = g_K;  break;
        case 2:  W = Wv; bias = bv; out = g_V;  break;
        default: W = Wg; bias = bg; out = g_GK; break;
    }

    const int t = threadIdx.x;
    const int lane = t & 31, warp = t >> 5;
    const int qr = lane >> 2, qc = lane & 3;
    const int wm = warp >> 1, wn = warp & 1;
    const int r0 = blockIdx.y * 128, c0 = blockIdx.x * 128;

    float acc[2][8][4];
#pragma unroll
    for (int mt = 0; mt < 2; mt++)
#pragma unroll
        for (int nt = 0; nt < 8; nt++)
#pragma unroll
            for (int k = 0; k < 4; k++) acc[mt][nt][k] = 0.f;

    for (int k0 = 0; k0 < HSZ; k0 += 32) {
#pragma unroll
        for (int i = 0; i < 4; i++) {
            int idx = t + i*256;
            int r = idx >> 3, c = (idx & 7) << 2;
            float4 v = *(const float4*)&X[(size_t)(r0+r)*HSZ + k0 + c];
            float* p = &As[r*PLA + (c & ~7)];
            int e = c & 7;
            p[pe(e+0)] = f2tf(v.x); p[pe(e+1)] = f2tf(v.y);
            p[pe(e+2)] = f2tf(v.z); p[pe(e+3)] = f2tf(v.w);
        }
#pragma unroll
        for (int i = 0; i < 4; i++) {
            int idx = t + i*256;
            int r = idx >> 5, c = (idx & 31) << 2;
            float4 v = *(const float4*)&W[(size_t)(k0+r)*HSZ + c0 + c];
            float4 o = make_float4(f2tf(v.x), f2tf(v.y), f2tf(v.z), f2tf(v.w));
            *(float4*)&Bs[r*PLB + c] = o;
        }
        __syncthreads();

#pragma unroll
        for (int u = 0; u < 4; u++) {
            uint32_t af[2][4];
#pragma unroll
            for (int mt = 0; mt < 2; mt++) {
                int rm = wm*32 + mt*16;
                float2 lo = *(const float2*)&As[(rm+qr  )*PLA + u*8 + 2*qc];
                float2 hi = *(const float2*)&As[(rm+qr+8)*PLA + u*8 + 2*qc];
                af[mt][0] = __float_as_uint(lo.x); af[mt][1] = __float_as_uint(hi.x);
                af[mt][2] = __float_as_uint(lo.y); af[mt][3] = __float_as_uint(hi.y);
            }
#pragma unroll
            for (int nt = 0; nt < 8; nt++) {
                int col = wn*64 + nt*8 + qr;
                uint32_t bb[2];
                bb[0] = __float_as_uint(Bs[(u*8+qc  )*PLB + col]);
                bb[1] = __float_as_uint(Bs[(u*8+qc+4)*PLB + col]);
                mma8(acc[0][nt], af[0], bb);
                mma8(acc[1][nt], af[1], bb);
            }
        }
        __syncthreads();
    }

#pragma unroll
    for (int mt = 0; mt < 2; mt++) {
        int rm = r0 + wm*32 + mt*16;
#pragma unroll
        for (int nt = 0; nt < 8; nt++) {
            int col = c0 + wn*64 + nt*8 + 2*qc;
            float b0 = bias[col], b1 = bias[col+1];
            float2 o;
            o.x = acc[mt][nt][0] + b0; o.y = acc[mt][nt][1] + b1;
            *(float2*)&out[(size_t)(rm+qr)*HSZ + col] = o;
            o.x = acc[mt][nt][2] + b0; o.y = acc[mt][nt][3] + b1;
            *(float2*)&out[(size_t)(rm+qr+8)*HSZ + col] = o;
        }
    }
}

// ===========================================================================
// gq = governance_embeddings[2,1024] @ Wgq + bgq   (tiny, SIMT, fp32)
// ===========================================================================
__global__ void gq_kernel(const float* __restrict__ ge,
                          const float* __restrict__ W,
                          const float* __restrict__ bias)
{
    int c = blockIdx.x * blockDim.x + threadIdx.x;
    int r = blockIdx.y;
    const float* g = ge + (size_t)r * HSZ;
    float a0 = 0.f, a1 = 0.f, a2 = 0.f, a3 = 0.f;
    for (int k = 0; k < HSZ; k += 4) {
        a0 += g[k+0] * W[(size_t)(k+0)*HSZ + c];
        a1 += g[k+1] * W[(size_t)(k+1)*HSZ + c];
        a2 += g[k+2] * W[(size_t)(k+2)*HSZ + c];
        a3 += g[k+3] * W[(size_t)(k+3)*HSZ + c];
    }
    g_GQ[(size_t)r*HSZ + c] = (a0+a1) + (a2+a3) + bias[c];
}

// ===========================================================================
// gov_scores[b,h,s] = sum_d gq[b,h,d]*gk[b,s,h,d]. One warp per output.
// ===========================================================================
__global__ void gov_kernel()
{
    int gw   = (blockIdx.x * blockDim.x + threadIdx.x) >> 5;
    int lane = threadIdx.x & 31;
    if (gw >= NSTAT) return;
    int s  = gw & (SEQ-1);
    int bh = gw >> 11;
    int b = bh >> 4, h = bh & 15;
    const float* gq = g_GQ + (size_t)b*HSZ + h*HDM;
    const float* gk = g_GK + ((size_t)(b*SEQ + s))*HSZ + h*HDM;
    float acc = gq[lane]*gk[lane] + gq[lane+32]*gk[lane+32];
#pragma unroll
    for (int o = 16; o; o >>= 1)
        acc += __shfl_xor_sync(0xffffffffu, acc, o);
    if (lane == 0) g_gov[gw] = acc;
}

// ===========================================================================
// Flash attention, tf32 tensor cores.
// BM=64: 128 threads / 4 warps x 16 rows -> 54.3KB smem -> 4 CTAs/SM,
// decorrelating sync/softmax stalls across CTAs on the same SM.
// No P smem bridge: S C-fragment reused directly as the PV A-fragment.
// ===========================================================================
#define ALD 72   /* qs/ks stride: 72 mod 32 == 8 */
#define VLD 68   /* vs stride: 68 mod 32 == 4 -> conflict-free PV B loads */
#define QS_OFF 0
#define KS_OFF (64*ALD)
#define VS_OFF (KS_OFF + 64*ALD)
#define ATT_SMEM ((VS_OFF + 64*VLD)*4)   /* 54272 bytes */

__global__ __launch_bounds__(128) void attn_kernel(float* __restrict__ ctx)
{
    extern __shared__ float sm[];
    float* qs = sm + QS_OFF;   // 64 x 64, k-permuted
    float* ks = sm + KS_OFF;   // 64 x 64, k-permuted
    float* vs = sm + VS_OFF;   // 64 x 64, natural [j][d]

    const int t = threadIdx.x;
    const int lane = t & 31, warp = t >> 5;
    const int qr = lane >> 2, qc = lane & 3;
    const int bh = blockIdx.y, b = bh >> 4, h = bh & 15;
    const int q0 = blockIdx.x * 64;
    const int wr = warp * 16;          // 4 warps x 16 rows

    const float* Qg = g_Q + ((size_t)(b*SEQ + q0))*HSZ + h*HDM;
    const float* Kg = g_K + ((size_t)(b*SEQ))*HSZ + h*HDM;
    const float* Vg = g_V + ((size_t)(b*SEQ))*HSZ + h*HDM;

    // stage Q (coalesced, tf32, permuted)
    for (int idx = t; idx < 1024; idx += 128) {
        int r = idx >> 4, c = (idx & 15) << 2;
        float4 v = *(const float4*)&Qg[(size_t)r*HSZ + c];
        float* p = &qs[r*ALD + (c & ~7)];
        int e = c & 7;
        p[pe(e+0)] = f2tf(v.x); p[pe(e+1)] = f2tf(v.y);
        p[pe(e+2)] = f2tf(v.z); p[pe(e+3)] = f2tf(v.w);
    }

    float O[8][4];
    float m[2], Z[2], T[2], E[2];
#pragma unroll
    for (int hi = 0; hi < 2; hi++) { m[hi] = -1e30f; Z[hi] = 0.f; T[hi] = 0.f; E[hi] = 0.f; }
#pragma unroll
    for (int nt = 0; nt < 8; nt++)
#pragma unroll
        for (int k = 0; k < 4; k++) O[nt][k] = 0.f;

    for (int j0 = 0; j0 < SEQ; j0 += 64) {
        __syncthreads();   // prior tile's reads of ks/vs done (also covers Q stage)
        for (int idx = t; idx < 1024; idx += 128) {
            int r = idx >> 4, c = (idx & 15) << 2;
            float4 kv = *(const float4*)&Kg[(size_t)(j0+r)*HSZ + c];
            float* p = &ks[r*ALD + (c & ~7)];
            int e = c & 7;
            p[pe(e+0)] = f2tf(kv.x); p[pe(e+1)] = f2tf(kv.y);
            p[pe(e+2)] = f2tf(kv.z); p[pe(e+3)] = f2tf(kv.w);
            float4 vv = *(const float4*)&Vg[(size_t)(j0+r)*HSZ + c];
            float4 vo = make_float4(f2tf(vv.x), f2tf(vv.y), f2tf(vv.z), f2tf(vv.w));
            *(float4*)&vs[r*VLD + c] = vo;
        }
        __syncthreads();

        // ---- S = Q @ K^T  (one 16-row m-tile per warp) ----
        float sc[8][4];
#pragma unroll
        for (int nt = 0; nt < 8; nt++)
#pragma unroll
            for (int k = 0; k < 4; k++) sc[nt][k] = 0.f;

#pragma unroll
        for (int u = 0; u < 8; u++) {
            uint32_t qa[4];
            {
                float2 lo = *(const float2*)&qs[(wr+qr  )*ALD + u*8 + 2*qc];
                float2 hi = *(const float2*)&qs[(wr+qr+8)*ALD + u*8 + 2*qc];
                qa[0] = __float_as_uint(lo.x); qa[1] = __float_as_uint(hi.x);
                qa[2] = __float_as_uint(lo.y); qa[3] = __float_as_uint(hi.y);
            }
#pragma unroll
            for (int nt = 0; nt < 8; nt++) {
                float2 kb = *(const float2*)&ks[(nt*8+qr)*ALD + u*8 + 2*qc];
                uint32_t bb[2] = { __float_as_uint(kb.x), __float_as_uint(kb.y) };
                mma8(sc[nt], qa, bb);
            }
        }

        // ---- online softmax + stats (rows wr+qr, wr+qr+8) ----
#pragma unroll
        for (int hi = 0; hi < 2; hi++) {
            float lm = -1e30f;
#pragma unroll
            for (int nt = 0; nt < 8; nt++) {
                sc[nt][2*hi  ] *= 0.125f;
                sc[nt][2*hi+1] *= 0.125f;
                lm = fmaxf(lm, fmaxf(sc[nt][2*hi], sc[nt][2*hi+1]));
            }
            lm = fmaxf(lm, __shfl_xor_sync(0xffffffffu, lm, 1));
            lm = fmaxf(lm, __shfl_xor_sync(0xffffffffu, lm, 2));
            float mo = m[hi];
            float mn = fmaxf(mo, lm);
            float al = __expf(mo - mn);
            T[hi] = al * (T[hi] + (mo - mn) * Z[hi]);
            Z[hi] *= al;
            E[hi] *= al;
#pragma unroll
            for (int nt = 0; nt < 8; nt++) {
                O[nt][2*hi  ] *= al;
                O[nt][2*hi+1] *= al;
            }
            m[hi] = mn;
            float sp = 0.f, st = 0.f, pm = 0.f;
#pragma unroll
            for (int nt = 0; nt < 8; nt++) {
#pragma unroll
                for (int k = 0; k < 2; k++) {
                    float d = sc[nt][2*hi+k] - mn;
                    float p = __expf(d);
                    sp += p; st += p*d; pm = fmaxf(pm, p);
                    sc[nt][2*hi+k] = f2tf(p);   // rounded for the PV mma
                }
            }
            sp += __shfl_xor_sync(0xffffffffu, sp, 1);
            sp += __shfl_xor_sync(0xffffffffu, sp, 2);
            st += __shfl_xor_sync(0xffffffffu, st, 1);
            st += __shfl_xor_sync(0xffffffffu, st, 2);
            pm  = fmaxf(pm, __shfl_xor_sync(0xffffffffu, pm, 1));
            pm  = fmaxf(pm, __shfl_xor_sync(0xffffffffu, pm, 2));
            Z[hi] += sp; T[hi] += st; E[hi] = fmaxf(E[hi], pm);
        }

        // ---- O += P @ V : sc fragment reused directly as A-fragment ----
#pragma unroll
        for (int u = 0; u < 8; u++) {
            uint32_t pa[4];
            pa[0] = __float_as_uint(sc[u][0]);
            pa[1] = __float_as_uint(sc[u][2]);
            pa[2] = __float_as_uint(sc[u][1]);
            pa[3] = __float_as_uint(sc[u][3]);
#pragma unroll
            for (int nt = 0; nt < 8; nt++) {
                uint32_t bb[2];
                bb[0] = __float_as_uint(vs[(u*8 + 2*qc    )*VLD + nt*8 + qr]);
                bb[1] = __float_as_uint(vs[(u*8 + 2*qc + 1)*VLD + nt*8 + qr]);
                mma8(O[nt], pa, bb);
            }
        }
    }

    // ---- epilogue: normalize, write context + per-row stats ----
#pragma unroll
    for (int hi = 0; hi < 2; hi++) {
        int row = wr + qr + 8*hi;
        float iz = 1.0f / Z[hi];
#pragma unroll
        for (int nt = 0; nt < 8; nt++) {
            float2 o;
            o.x = O[nt][2*hi  ] * iz;
            o.y = O[nt][2*hi+1] * iz;
            *(float2*)&ctx[((size_t)(b*SEQ + q0 + row))*HSZ + h*HDM + nt*8 + 2*qc] = o;
        }
        if (qc == 0) {
            int idx = bh*SEQ + q0 + row;
            g_ent[idx] = logf(Z[hi]) - T[hi]*iz;
            g_mxp[idx] = E[hi]*iz;
        }
    }
}

// ===========================================================================
// Deterministic final reduction: 3 scalar means (no atomics).
// ===========================================================================
__global__ void reduce_kernel(float* __restrict__ out, int n_ctx)
{
    __shared__ float se[512], si[512], sc[512];
    int t = threadIdx.x;
    float e = 0.f, i = 0.f, c = 0.f;
    for (int l = t; l < NSTAT; l += 512) {
        e += g_ent[l];
        i += fabsf(g_gov[l]);
        c += g_mxp[l];
    }
    se[t] = e; si[t] = i; sc[t] = c;
    __syncthreads();
    for (int s2 = 256; s2 > 0; s2 >>= 1) {
        if (t < s2) { se[t] += se[t+s2]; si[t] += si[t+s2]; sc[t] += sc[t+s2]; }
        __syncthreads();
    }
    if (t == 0) {
        const float inv = 1.0f / (float)NSTAT;
        out[n_ctx + 0] = se[0] * inv;
        out[n_ctx + 1] = si[0] * inv;
        out[n_ctx + 2] = sc[0] * inv;
    }
}

// ===========================================================================
extern "C" void kernel_launch(void* const* d_in, const int* in_sizes, int n_in,
                              void* d_out, int out_size)
{
    const float* X   = (const float*)d_in[0];
    const float* GE  = (const float*)d_in[1];
    const float* Wq  = (const float*)d_in[2];  const float* bq  = (const float*)d_in[3];
    const float* Wk  = (const float*)d_in[4];  const float* bk  = (const float*)d_in[5];
    const float* Wv  = (const float*)d_in[6];  const float* bv  = (const float*)d_in[7];
    const float* Wgq = (const float*)d_in[8];  const float* bgq = (const float*)d_in[9];
    const float* Wgk = (const float*)d_in[10]; const float* bgk = (const float*)d_in[11];
    float* out = (float*)d_out;

    cudaFuncSetAttribute(attn_kernel, cudaFuncAttributeMaxDynamicSharedMemorySize, ATT_SMEM);

    proj_kernel<<<dim3(8, 32, 4), 256>>>(X, Wq, bq, Wk, bk, Wv, bv, Wgk, bgk);
    gq_kernel<<<dim3(4, 2), 256>>>(GE, Wgq, bgq);
    gov_kernel<<<NSTAT*32/256, 256>>>();
    attn_kernel<<<dim3(SEQ/64, BSZ*NHD), 128, ATT_SMEM>>>(out);
    reduce_kernel<<<1, 512>>>(out, out_size - 3);
}